// round 6
// baseline (speedup 1.0000x reference)
#include <cuda_runtime.h>
#include <math_constants.h>

#define HH 224
#define WW 224
#define HWP (HH * WW)      // 50176
#define BB 64
#define RBLK 16            // reduce blocks per batch
#define NRED (BB * RBLK)   // 1024 reduce-role blocks
#define MBLK 49            // main blocks per batch
#define NMAIN (BB * MBLK)  // 3136 main-role blocks

// Per-(batch, block) partial min/max. Plain stores (no init needed).
__device__ float g_pmax[BB][RBLK];
__device__ float g_pmin[BB][RBLK];
// Tickets/flags. Zero at module load; every replay restores them to zero.
__device__ int g_cnt[BB];    // reduce-completion ticket
__device__ int g_done[BB];   // main-consumption ticket (resets g_flag)
__device__ int g_flag[BB];   // scalars-ready flag
// Per-batch scalars: [pd, fr, hp0f, hp1f] [gx, gy, rn2, pad]
__device__ float4 g_scal[BB][2];

__global__ void __launch_bounds__(256)
fused_kernel(const float* __restrict__ depth, const float* __restrict__ obj,
             const float* __restrict__ gaze, const long long* __restrict__ hp,
             float* __restrict__ out) {
    const int bid = blockIdx.x;

    if (bid < NRED) {
        // ---------------- reduce role ----------------
        // Batch-major: batch 0's 16 blocks are bids 0..15 -> finish first,
        // unblocking batch 0's main blocks while later batches still reduce.
        const int b    = bid / RBLK;
        const int rblk = bid % RBLK;
        const float4* dp = reinterpret_cast<const float4*>(depth + (size_t)b * HWP);
        const float4* op = reinterpret_cast<const float4*>(obj + (size_t)b * HWP);
        float mx = -CUDART_INF_F, mn = CUDART_INF_F;
        const int n4 = HWP / 4;  // 12544
        for (int i = rblk * 256 + threadIdx.x; i < n4; i += RBLK * 256) {
            float4 d = dp[i];
            float4 o = op[i];
            float p0 = d.x * o.x, p1 = d.y * o.y, p2 = d.z * o.z, p3 = d.w * o.w;
            mx = fmaxf(mx, fmaxf(fmaxf(p0, p1), fmaxf(p2, p3)));
            mn = fminf(mn, fminf(fminf(p0, p1), fminf(p2, p3)));
        }
#pragma unroll
        for (int off = 16; off; off >>= 1) {
            mx = fmaxf(mx, __shfl_xor_sync(0xffffffffu, mx, off));
            mn = fminf(mn, __shfl_xor_sync(0xffffffffu, mn, off));
        }
        __shared__ float smx[8], smn[8];
        int w = threadIdx.x >> 5, l = threadIdx.x & 31;
        if (l == 0) { smx[w] = mx; smn[w] = mn; }
        __syncthreads();
        if (threadIdx.x == 0) {
#pragma unroll
            for (int i = 1; i < 8; i++) {
                mx = fmaxf(mx, smx[i]);
                mn = fminf(mn, smn[i]);
            }
            g_pmax[b][rblk] = mx;
            g_pmin[b][rblk] = mn;
            __threadfence();
            int ticket = atomicAdd(&g_cnt[b], 1);
            if (ticket == RBLK - 1) {
                g_cnt[b] = 0;            // reset for next graph replay
                float fmx = -CUDART_INF_F, fmn = CUDART_INF_F;
#pragma unroll
                for (int i = 0; i < RBLK; i++) {
                    fmx = fmaxf(fmx, g_pmax[b][i]);
                    fmn = fminf(fmn, g_pmin[b][i]);
                }
                int hp0 = (int)hp[2 * b];
                int hp1 = (int)hp[2 * b + 1];
                size_t hidx = (size_t)b * HWP + (size_t)hp0 * WW + hp1;
                float hd = depth[hidx] * obj[hidx];
                float gx = gaze[3 * b], gy = gaze[3 * b + 1], gz = gaze[3 * b + 2];
                g_scal[b][0] = make_float4(hd + gz * 224.0f,      // pd
                                           (fmx - fmn) / 24.0f,   // fr
                                           (float)hp0, (float)hp1);
                g_scal[b][1] = make_float4(gx, gy, gx * gx + gy * gy, 0.f);
                __threadfence();
                atomicExch(&g_flag[b], 1);   // release
            }
        }
        return;
    }

    // ---------------- main role ----------------
    const int mb = bid - NRED;
    const int b  = mb / MBLK;
    const int lb = mb % MBLK;

    const int idx = lb * 256 + threadIdx.x;  // float4 index within image
    const int pix = idx * 4;
    const int h   = pix / WW;
    const int w0  = pix % WW;   // 4 consecutive pixels stay in one row

    // Prefetch pixel data BEFORE the spin: these loads are independent of
    // the scalars, so their L2 latency hides behind the flag wait.
    const float4 d4 = *reinterpret_cast<const float4*>(depth + (size_t)b * HWP + pix);
    const float4 o4 = *reinterpret_cast<const float4*>(obj   + (size_t)b * HWP + pix);

    // Wait for this batch's scalars. Reduce-role blocks never wait on
    // anything, so they always retire and set the flag -> no deadlock.
    if (threadIdx.x == 0) {
        volatile int* f = &g_flag[b];
        if (*f == 0) {
            while (*f == 0) { __nanosleep(64); }
        }
        __threadfence();                     // acquire
    }
    __syncthreads();

    const float4 s0 = g_scal[b][0];
    const float4 s1 = g_scal[b][1];

    // Consumption ticket: the 49th main block for this batch resets the
    // flag so the next graph replay starts from the zero state.
    if (threadIdx.x == 0) {
        int t = atomicAdd(&g_done[b], 1);
        if (t == MBLK - 1) { g_done[b] = 0; g_flag[b] = 0; }
    }

    const float pd = s0.x, fr = s0.y;
    const float cf1 = fr, cf2 = 2.f * fr, cf3 = 3.f * fr;
    const float gx = s1.x, gy = s1.y, rn2 = s1.z;
    const float a1   = (float)h - s0.w;      // arr1 = h - hp1
    const float a1gy = a1 * gy;
    const float a1sq = a1 * a1;
    const float a0b  = (float)w0 - s0.z;     // arr0 base = w - hp0 (exact)
    const float angscale = 12.0f / CUDART_PI_F;

    float dv[4] = {d4.x * o4.x, d4.y * o4.y, d4.z * o4.z, d4.w * o4.w};

    // Cheap FMA-only cone gate for this thread's 4 pixels.
    // 0.93 < cos^2(pi/12)=0.93301: slightly loose so fp noise only sends
    // extra pixels to the exact slow path, never skips a hit.
    bool any = false;
#pragma unroll
    for (int j = 0; j < 4; j++) {
        float a0  = a0b + (float)j;          // exact
        float dot = fmaf(a0, gx, a1gy);
        float tt  = fmaf(a0, a0, a1sq) * rn2;
        any = any || (dot > 0.f && dot * dot > 0.93f * tt);
    }

    float m[4] = {0.f, 0.f, 0.f, 0.f};
    if (any) {
        // Branch-free exact mask: out-of-cone -> negative -> 0; tt==0 or
        // r>1 -> NaN -> fmaxf scrubs to 0 (== jnp.nan_to_num(maximum(...))).
#pragma unroll
        for (int j = 0; j < 4; j++) {
            float a0  = a0b + (float)j;
            float dot = fmaf(a0, gx, a1gy);
            float tt  = fmaf(a0, a0, a1sq) * rn2;
            float r   = dot * rsqrtf(tt);
            m[j] = fmaxf(fmaf(-angscale, acosf(r), 1.0f), 0.0f);
        }
    }

    float o0[4], o1[4], o2[4];
#pragma unroll
    for (int j = 0; j < 4; j++) {
        float d = dv[j];
        float e = fabsf(d - pd);             // |d - point_depth|
        float v = d * m[j];
        o0[j] = (e <= cf1) ? v : 0.f;
        o1[j] = (e <= cf2) ? v : 0.f;
        o2[j] = (e <= cf3) ? v : 0.f;
    }

    float* op0 = out + (size_t)b * 3 * HWP + pix;
    *reinterpret_cast<float4*>(op0)           = make_float4(o0[0], o0[1], o0[2], o0[3]);
    *reinterpret_cast<float4*>(op0 + HWP)     = make_float4(o1[0], o1[1], o1[2], o1[3]);
    *reinterpret_cast<float4*>(op0 + 2 * HWP) = make_float4(o2[0], o2[1], o2[2], o2[3]);
}

extern "C" void kernel_launch(void* const* d_in, const int* in_sizes, int n_in,
                              void* d_out, int out_size) {
    const float* depth = (const float*)d_in[0];
    const float* obj   = (const float*)d_in[1];
    const float* gaze  = (const float*)d_in[2];
    const long long* hp = (const long long*)d_in[3];
    float* out = (float*)d_out;

    fused_kernel<<<NRED + NMAIN, 256>>>(depth, obj, gaze, hp, out);
}

// round 7
// speedup vs baseline: 1.2367x; 1.2367x over previous
#include <cuda_runtime.h>
#include <math_constants.h>

#define HH 224
#define WW 224
#define HWP (HH * WW)      // 50176
#define BB 64
#define RBLK 16            // reduce blocks per batch
#define MBLK 49            // main tiles per batch
#define NMAIN (BB * MBLK)  // 3136 main tiles
#define MGRID 1184         // 148 SMs * 8 blocks -> exactly full waves

// Per-(batch, block) partial min/max. Plain stores (no init needed).
__device__ float g_pmax[BB][RBLK];
__device__ float g_pmin[BB][RBLK];
// Ticket per batch. Zero at module load; winner resets -> replay-safe.
__device__ int g_cnt[BB];
// Per-batch scalars: [pd, fr, hp0f, hp1f] [gx, gy, rn2, pad]
__device__ float4 g_scal[BB][2];

__global__ void __launch_bounds__(256)
reduce_kernel(const float* __restrict__ depth, const float* __restrict__ obj,
              const float* __restrict__ gaze, const long long* __restrict__ hp) {
    const int b = blockIdx.y;

    // Thread 0 prefetches the scalar inputs at block ENTRY so the dependent
    // load chain (hp -> head pixel -> product) overlaps the reduction loop.
    int hp0 = 0, hp1 = 0;
    float gx = 0.f, gy = 0.f, gz = 0.f, hd = 0.f;
    if (threadIdx.x == 0) {
        hp0 = (int)hp[2 * b];
        hp1 = (int)hp[2 * b + 1];
        gx = gaze[3 * b]; gy = gaze[3 * b + 1]; gz = gaze[3 * b + 2];
        size_t hidx = (size_t)b * HWP + (size_t)hp0 * WW + hp1;
        hd = depth[hidx] * obj[hidx];
    }

    const float4* dp = reinterpret_cast<const float4*>(depth + (size_t)b * HWP);
    const float4* op = reinterpret_cast<const float4*>(obj + (size_t)b * HWP);
    float mx = -CUDART_INF_F, mn = CUDART_INF_F;
    const int n4 = HWP / 4;  // 12544
    for (int i = blockIdx.x * 256 + threadIdx.x; i < n4; i += RBLK * 256) {
        float4 d = dp[i];
        float4 o = op[i];
        float p0 = d.x * o.x, p1 = d.y * o.y, p2 = d.z * o.z, p3 = d.w * o.w;
        mx = fmaxf(mx, fmaxf(fmaxf(p0, p1), fmaxf(p2, p3)));
        mn = fminf(mn, fminf(fminf(p0, p1), fminf(p2, p3)));
    }
#pragma unroll
    for (int off = 16; off; off >>= 1) {
        mx = fmaxf(mx, __shfl_xor_sync(0xffffffffu, mx, off));
        mn = fminf(mn, __shfl_xor_sync(0xffffffffu, mn, off));
    }
    __shared__ float smx[8], smn[8];
    int w = threadIdx.x >> 5, l = threadIdx.x & 31;
    if (l == 0) { smx[w] = mx; smn[w] = mn; }
    __syncthreads();
    if (threadIdx.x == 0) {
#pragma unroll
        for (int i = 1; i < 8; i++) {
            mx = fmaxf(mx, smx[i]);
            mn = fminf(mn, smn[i]);
        }
        g_pmax[b][blockIdx.x] = mx;
        g_pmin[b][blockIdx.x] = mn;
        __threadfence();
        int ticket = atomicAdd(&g_cnt[b], 1);
        if (ticket == RBLK - 1) {
            g_cnt[b] = 0;            // reset for next graph replay
            // Only the 16 partial loads remain on the critical path; all
            // scalar inputs were prefetched at block entry.
            float fmx = -CUDART_INF_F, fmn = CUDART_INF_F;
#pragma unroll
            for (int i = 0; i < RBLK; i++) {
                fmx = fmaxf(fmx, g_pmax[b][i]);
                fmn = fminf(fmn, g_pmin[b][i]);
            }
            g_scal[b][0] = make_float4(hd + gz * 224.0f,      // pd
                                       (fmx - fmn) / 24.0f,   // fr
                                       (float)hp0, (float)hp1);
            g_scal[b][1] = make_float4(gx, gy, gx * gx + gy * gy, 0.f);
        }
    }
}

// Persistent-style: MGRID blocks grid-stride over 3136 tiles (2-3 each).
// Each tile = 256 threads * 4 px. No smem, no barriers.
__global__ void __launch_bounds__(256)
main_kernel(const float* __restrict__ depth, const float* __restrict__ obj,
            float* __restrict__ out) {
    const float angscale = 12.0f / CUDART_PI_F;

    for (int mb = blockIdx.x; mb < NMAIN; mb += MGRID) {
        const int b  = mb / MBLK;
        const int lb = mb % MBLK;

        const int idx = lb * 256 + threadIdx.x;  // float4 index within image
        const int pix = idx * 4;
        const int h   = pix / WW;
        const int w0  = pix % WW;   // 4 consecutive pixels, one row

        const float4 d4 = *reinterpret_cast<const float4*>(depth + (size_t)b * HWP + pix);
        const float4 o4 = *reinterpret_cast<const float4*>(obj   + (size_t)b * HWP + pix);
        const float4 s0 = g_scal[b][0];
        const float4 s1 = g_scal[b][1];

        const float pd = s0.x, fr = s0.y;
        const float cf1 = fr, cf2 = 2.f * fr, cf3 = 3.f * fr;
        const float gx = s1.x, gy = s1.y, rn2 = s1.z;
        const float a1   = (float)h - s0.w;      // arr1 = h - hp1
        const float a1gy = a1 * gy;
        const float a1sq = a1 * a1;
        const float a0b  = (float)w0 - s0.z;     // arr0 base = w - hp0 (exact)

        float dv[4] = {d4.x * o4.x, d4.y * o4.y, d4.z * o4.z, d4.w * o4.w};

        // Cheap FMA-only cone gate for this thread's 4 pixels.
        // 0.93 < cos^2(pi/12)=0.93301: slightly loose so fp noise only sends
        // extra pixels to the exact slow path, never skips a hit.
        bool any = false;
#pragma unroll
        for (int j = 0; j < 4; j++) {
            float a0  = a0b + (float)j;          // exact
            float dot = fmaf(a0, gx, a1gy);
            float tt  = fmaf(a0, a0, a1sq) * rn2;
            any = any || (dot > 0.f && dot * dot > 0.93f * tt);
        }

        float m[4] = {0.f, 0.f, 0.f, 0.f};
        if (any) {
            // Branch-free exact mask: out-of-cone -> negative -> 0; tt==0 or
            // r>1 -> NaN -> fmaxf scrubs to 0 (== nan_to_num(maximum(...))).
#pragma unroll
            for (int j = 0; j < 4; j++) {
                float a0  = a0b + (float)j;
                float dot = fmaf(a0, gx, a1gy);
                float tt  = fmaf(a0, a0, a1sq) * rn2;
                float r   = dot * rsqrtf(tt);
                m[j] = fmaxf(fmaf(-angscale, acosf(r), 1.0f), 0.0f);
            }
        }

        float o0[4], o1[4], o2[4];
#pragma unroll
        for (int j = 0; j < 4; j++) {
            float d = dv[j];
            float e = fabsf(d - pd);             // |d - point_depth|
            float v = d * m[j];
            o0[j] = (e <= cf1) ? v : 0.f;
            o1[j] = (e <= cf2) ? v : 0.f;
            o2[j] = (e <= cf3) ? v : 0.f;
        }

        float* op0 = out + (size_t)b * 3 * HWP + pix;
        // Streaming stores: output is never re-read; evict-first keeps the
        // inputs L2-resident for the next graph replay.
        __stcs(reinterpret_cast<float4*>(op0),
               make_float4(o0[0], o0[1], o0[2], o0[3]));
        __stcs(reinterpret_cast<float4*>(op0 + HWP),
               make_float4(o1[0], o1[1], o1[2], o1[3]));
        __stcs(reinterpret_cast<float4*>(op0 + 2 * HWP),
               make_float4(o2[0], o2[1], o2[2], o2[3]));
    }
}

extern "C" void kernel_launch(void* const* d_in, const int* in_sizes, int n_in,
                              void* d_out, int out_size) {
    const float* depth = (const float*)d_in[0];
    const float* obj   = (const float*)d_in[1];
    const float* gaze  = (const float*)d_in[2];
    const long long* hp = (const long long*)d_in[3];
    float* out = (float*)d_out;

    reduce_kernel<<<dim3(RBLK, BB), 256>>>(depth, obj, gaze, hp);
    main_kernel<<<MGRID, 256>>>(depth, obj, out);
}